// round 14
// baseline (speedup 1.0000x reference)
#include <cuda_runtime.h>
#include <cstdint>

#define Bsz 8
#define Nn 1024
#define Hh 8
#define FOv 64
#define FINv 256
#define LOG2E 1.4426950408889634f

// ---------------- device scratch ----------------
__device__ unsigned g_abits[Bsz * Nn * 32];                 // packed adjacency
__device__ float g_h[(size_t)Bsz * Hh * Nn * FOv];          // h[b][h][n][o] (tf32-rounded)
__device__ float2 g_es[Bsz * Hh * Nn];                      // (exp2(S), exp2(0.2 S)) per row
__device__ float2 g_ed[Bsz * Hh * Nn];                      // (exp2(D), exp2(0.2 D)) per neighbor
__device__ float g_hout[(size_t)Bsz * Hh * Nn * FOv];

// ---------------- helpers ----------------
static __device__ __forceinline__ uint32_t to_tf32(float f) {
    uint32_t u;
    asm("cvt.rna.tf32.f32 %0, %1;" : "=r"(u) : "f"(f));
    return u;
}
static __device__ __forceinline__ float ex2f(float x) {
    float y;
    asm("ex2.approx.f32 %0, %1;" : "=f"(y) : "f"(x));
    return y;
}
static __device__ __forceinline__ uint32_t smem_u32(const void* p) {
    uint32_t a;
    asm("{ .reg .u64 t; cvta.to.shared.u64 t, %1; cvt.u32.u64 %0, t; }" : "=r"(a) : "l"(p));
    return a;
}
static __device__ __forceinline__ void cpasync16(uint32_t s, const void* g) {
    asm volatile("cp.async.cg.shared.global [%0], [%1], 16;" :: "r"(s), "l"(g));
}
#define CP_COMMIT() asm volatile("cp.async.commit_group;" ::: "memory")
#define CP_WAIT(n)  asm volatile("cp.async.wait_group %0;" :: "n"(n) : "memory")
static __device__ __forceinline__ void mma_tf32(float* c, const uint32_t* a, uint32_t b0, uint32_t b1) {
    asm volatile(
        "mma.sync.aligned.m16n8k8.row.col.f32.tf32.tf32.f32 "
        "{%0,%1,%2,%3}, {%4,%5,%6,%7}, {%8,%9}, {%0,%1,%2,%3};"
        : "+f"(c[0]), "+f"(c[1]), "+f"(c[2]), "+f"(c[3])
        : "r"(a[0]), "r"(a[1]), "r"(a[2]), "r"(a[3]), "r"(b0), "r"(b1));
}

// ---------------- K0: pack adjacency (reg-preloaded, MLP 32) ----------------
__global__ void k_pack(const int* __restrict__ A) {
    int warp = (blockIdx.x * blockDim.x + threadIdx.x) >> 5;
    int lane = threadIdx.x & 31;
    const int* row = A + (size_t)warp * Nn;
    unsigned* dst = g_abits + warp * 32;
    int v[32];
    #pragma unroll
    for (int w = 0; w < 32; w++) v[w] = row[w * 32 + lane];
    #pragma unroll
    for (int w = 0; w < 32; w++) {
        unsigned bits = __ballot_sync(0xffffffffu, v[w] > 0);
        if (lane == 0) dst[w] = bits;
    }
}

// ---------------- K1: feature GEMM (all heads) + fused s,d -> exp2 tables ----------
#define RECX_STRIDE 260
#define W_STRIDE 72
#define OFF_W    66560                       // recx: 64*260*4
#define OFF_ASD  (66560 + 147456)            // W: 2*256*72*4
#define FEAT_SMEM (OFF_ASD + 4096)           // asd: 1024 floats

__global__ __launch_bounds__(256) void k_feat(
    const float* __restrict__ x, const float* __restrict__ e,
    const float* __restrict__ Np, const float* __restrict__ wg,
    const float* __restrict__ a_src, const float* __restrict__ a_dst)
{
    extern __shared__ unsigned char sm_[];
    uint32_t* recx_s = (uint32_t*)sm_;
    uint32_t* W_s = (uint32_t*)(sm_ + OFF_W);
    float* asd_s = (float*)(sm_ + OFF_ASD);
    int nt = blockIdx.x, b = blockIdx.y;
    int n0 = nt * 64;
    int tid = threadIdx.x;
    int wp = tid >> 5, lane = tid & 31;
    int gr = lane >> 2, lc = lane & 3;
    int hp = wp >> 2;
    int wr = (wp & 3) * 16;

    asd_s[tid] = a_src[tid];
    asd_s[tid + 256] = a_src[tid + 256];
    asd_s[512 + tid] = a_dst[tid];
    asd_s[768 + tid] = a_dst[tid + 256];

    {
        int rr = tid >> 2;
        int f0 = (tid & 3) * 64;
        const float* xrow = x + b * FINv;
        const float* np = Np + (size_t)(n0 + rr) * FINv;
        const float* ee = e + ((size_t)b * Nn + n0 + rr) * FINv;
        uint32_t* dstr = recx_s + rr * RECX_STRIDE + f0;
        #pragma unroll
        for (int i = 0; i < 16; i++) {
            float4 xv = *(const float4*)&xrow[f0 + i * 4];
            float4 nv = *(const float4*)&np[f0 + i * 4];
            float4 ev = *(const float4*)&ee[f0 + i * 4];
            dstr[i * 4 + 0] = to_tf32(xv.x * nv.x * ev.x);
            dstr[i * 4 + 1] = to_tf32(xv.y * nv.y * ev.y);
            dstr[i * 4 + 2] = to_tf32(xv.z * nv.z * ev.z);
            dstr[i * 4 + 3] = to_tf32(xv.w * nv.w * ev.w);
        }
    }

    for (int it = 0; it < 4; it++) {
        __syncthreads();
        {
            const float* wsrc = wg + (size_t)(it * 2) * FINv * FOv;
            #pragma unroll
            for (int i = 0; i < 32; i++) {
                int idx = i * 256 + tid;
                int hh = idx >> 12;
                int r = idx & 4095;
                int f = r >> 4, o4 = r & 15;
                float4 v = *(const float4*)&wsrc[(size_t)hh * FINv * FOv + f * FOv + o4 * 4];
                uint32_t* dd = W_s + hh * (256 * W_STRIDE) + f * W_STRIDE + o4 * 4;
                dd[0] = to_tf32(v.x); dd[1] = to_tf32(v.y);
                dd[2] = to_tf32(v.z); dd[3] = to_tf32(v.w);
            }
        }
        __syncthreads();
        int h = it * 2 + hp;
        const uint32_t* Wh = W_s + hp * (256 * W_STRIDE);
        float c[8][4];
        #pragma unroll
        for (int ot = 0; ot < 8; ot++)
            #pragma unroll
            for (int r = 0; r < 4; r++) c[ot][r] = 0.f;
        #pragma unroll
        for (int ks = 0; ks < 32; ks++) {
            uint32_t a[4];
            const uint32_t* ar0 = recx_s + (wr + gr) * RECX_STRIDE + ks * 8;
            const uint32_t* ar1 = ar0 + 8 * RECX_STRIDE;
            a[0] = ar0[lc]; a[1] = ar1[lc]; a[2] = ar0[lc + 4]; a[3] = ar1[lc + 4];
            const uint32_t* br0 = Wh + (ks * 8 + lc) * W_STRIDE + gr;
            const uint32_t* br1 = br0 + 4 * W_STRIDE;
            #pragma unroll
            for (int ot = 0; ot < 8; ot++)
                mma_tf32(c[ot], a, br0[ot * 8], br1[ot * 8]);
        }
        int bh = b * Hh + h;
        float* dsth = g_h + ((size_t)bh * Nn + n0 + wr) * FOv;
        const float* as = asd_s + h * 64;
        const float* ad = asd_s + 512 + h * 64;
        float s0 = 0.f, s1 = 0.f, d0 = 0.f, d1 = 0.f;
        #pragma unroll
        for (int ot = 0; ot < 8; ot++) {
            int o = ot * 8 + lc * 2;
            // store h tf32-ROUNDED: aggregation mma B-truncation becomes exact
            float2 hlo = make_float2(__uint_as_float(to_tf32(c[ot][0])),
                                     __uint_as_float(to_tf32(c[ot][1])));
            float2 hhi = make_float2(__uint_as_float(to_tf32(c[ot][2])),
                                     __uint_as_float(to_tf32(c[ot][3])));
            *(float2*)&dsth[(size_t)gr * FOv + o] = hlo;
            *(float2*)&dsth[(size_t)(gr + 8) * FOv + o] = hhi;
            float a0 = as[o], a1 = as[o + 1];
            float b0 = ad[o], b1 = ad[o + 1];
            s0 += c[ot][0] * a0 + c[ot][1] * a1;
            s1 += c[ot][2] * a0 + c[ot][3] * a1;
            d0 += c[ot][0] * b0 + c[ot][1] * b1;
            d1 += c[ot][2] * b0 + c[ot][3] * b1;
        }
        #pragma unroll
        for (int off = 1; off <= 2; off <<= 1) {
            s0 += __shfl_xor_sync(0xffffffffu, s0, off);
            s1 += __shfl_xor_sync(0xffffffffu, s1, off);
            d0 += __shfl_xor_sync(0xffffffffu, d0, off);
            d1 += __shfl_xor_sync(0xffffffffu, d1, off);
        }
        if (lc == 0) {
            int rb = bh * Nn + n0 + wr + gr;
            float S0 = s0 * LOG2E, S1 = s1 * LOG2E;
            float D0 = d0 * LOG2E, D1 = d1 * LOG2E;
            g_es[rb]     = make_float2(ex2f(S0), ex2f(0.2f * S0));
            g_es[rb + 8] = make_float2(ex2f(S1), ex2f(0.2f * S1));
            g_ed[rb]     = make_float2(ex2f(D0), ex2f(0.2f * D0));
            g_ed[rb + 8] = make_float2(ex2f(D1), ex2f(0.2f * D1));
        }
    }
}

// ---------------- K3: fused masked softmax + tf32 mma aggregation ----------------
// 64-row tiles (grid 1024), 4 warps x 16 rows -> 32 acc regs/thread, 6 CTAs/SM.
// Factorized exp via precomputed (Es,Es2)/(Ed,Ed2) tables, zero MUFU in kernel body.
// 3-stage cp.async pipeline, stride-72 conflict-free smem, 1 sync/chunk.
#define HS_STR 72

__global__ void __launch_bounds__(128, 6) k_attn() {
    __shared__ uint32_t hs[3][32][HS_STR];   // h chunk (tf32-exact fp32 bits) [k=m][o]
    __shared__ float2 eds[Nn];               // (Ed, Ed2) per neighbor
    int tid = threadIdx.x;
    int w = tid >> 5, lane = tid & 31;
    int gr = lane >> 2, lc = lane & 3;
    int nt = blockIdx.x, h = blockIdx.y, b = blockIdx.z;
    int bh = b * Hh + h;
    int n0 = nt * 64;
    const float* hbase = g_h + (size_t)bh * Nn * FOv;

    {   // stage Ed table (pure copy, 8KB)
        const float4* esrc = (const float4*)(g_ed + bh * Nn);
        float4* ed4 = (float4*)eds;
        #pragma unroll
        for (int i = 0; i < 4; i++) ed4[tid + i * 128] = esrc[tid + i * 128];
    }
    int rbase = n0 + w * 16 + gr;            // rows rbase, rbase+8
    float2 es0 = g_es[bh * Nn + rbase];
    float2 es1 = g_es[bh * Nn + rbase + 8];
    const unsigned* bb0 = g_abits + (size_t)(b * Nn + rbase) * 32;
    const unsigned* bb1 = bb0 + 8 * 32;

    float c[8][4];
    #pragma unroll
    for (int ot = 0; ot < 8; ot++)
        #pragma unroll
        for (int r = 0; r < 4; r++) c[ot][r] = 0.f;
    float rs0 = 0.f, rs1 = 0.f;

    // staging coords: thread copies rows sm_+i*8 (i=0..3), 16B at col so4*4
    int sm_ = tid >> 4;
    int so4 = tid & 15;
    uint32_t hsb = smem_u32(hs);
    const float* gsrc = hbase + (size_t)sm_ * FOv + so4 * 4;

    // prologue: stage chunks 0,1 into bufs 0,1
    #pragma unroll
    for (int s = 0; s < 2; s++) {
        #pragma unroll
        for (int i = 0; i < 4; i++)
            cpasync16(hsb + (((unsigned)(s * 32 + sm_ + i * 8)) * HS_STR + so4 * 4) * 4,
                      gsrc + (s * 32 + i * 8) * FOv);
        CP_COMMIT();
    }

    for (int ch = 0; ch < 32; ch++) {
        int m0 = ch * 32;
        int buf = ch - (ch / 3) * 3;     // ch % 3
        if (ch < 31) CP_WAIT(1); else CP_WAIT(0);
        __syncthreads();

        unsigned bw0 = bb0[ch], bw1 = bb1[ch];
        #pragma unroll
        for (int j = 0; j < 4; j++) {
            float2 eA = eds[m0 + j * 8 + lc];
            float2 eB = eds[m0 + j * 8 + lc + 4];
            int cc0 = j * 8 + lc, cc1 = cc0 + 4;
            // row group 0 (gr)
            float p1 = es0.x * eA.x, p2 = es0.y * eA.y;
            float w00 = (p1 > 1.f) ? p1 : p2;
            w00 = ((bw0 >> cc0) & 1u) ? w00 : 0.f;
            float p3 = es0.x * eB.x, p4 = es0.y * eB.y;
            float w01 = (p3 > 1.f) ? p3 : p4;
            w01 = ((bw0 >> cc1) & 1u) ? w01 : 0.f;
            // row group 1 (gr+8)
            float q1 = es1.x * eA.x, q2 = es1.y * eA.y;
            float w10 = (q1 > 1.f) ? q1 : q2;
            w10 = ((bw1 >> cc0) & 1u) ? w10 : 0.f;
            float q3 = es1.x * eB.x, q4 = es1.y * eB.y;
            float w11 = (q3 > 1.f) ? q3 : q4;
            w11 = ((bw1 >> cc1) & 1u) ? w11 : 0.f;
            // tf32-round; rowsum from rounded values (num/denom consistent)
            uint32_t afr[4];
            afr[0] = to_tf32(w00);   // (gr,   lc)
            afr[1] = to_tf32(w10);   // (gr+8, lc)
            afr[2] = to_tf32(w01);   // (gr,   lc+4)
            afr[3] = to_tf32(w11);   // (gr+8, lc+4)
            rs0 += __uint_as_float(afr[0]) + __uint_as_float(afr[2]);
            rs1 += __uint_as_float(afr[1]) + __uint_as_float(afr[3]);
            #pragma unroll
            for (int ot = 0; ot < 8; ot++) {
                uint32_t b0 = hs[buf][j * 8 + lc][ot * 8 + gr];
                uint32_t b1 = hs[buf][j * 8 + lc + 4][ot * 8 + gr];
                mma_tf32(c[ot], afr, b0, b1);
            }
        }
        if (ch < 30) {   // stage chunk ch+2 into buf (ch+2)%3
            int s = ch + 2;
            int nb = s - (s / 3) * 3;
            #pragma unroll
            for (int i = 0; i < 4; i++)
                cpasync16(hsb + (((unsigned)(nb * 32 + sm_ + i * 8)) * HS_STR + so4 * 4) * 4,
                          gsrc + (s * 32 + i * 8) * FOv);
            CP_COMMIT();
        }
    }
    rs0 += __shfl_xor_sync(0xffffffffu, rs0, 1);
    rs0 += __shfl_xor_sync(0xffffffffu, rs0, 2);
    rs1 += __shfl_xor_sync(0xffffffffu, rs1, 1);
    rs1 += __shfl_xor_sync(0xffffffffu, rs1, 2);
    float inv0 = 1.f / rs0;
    float inv1 = 1.f / rs1;

    float* ob = g_hout + (size_t)bh * Nn * FOv;
    #pragma unroll
    for (int ot = 0; ot < 8; ot++) {
        int o = ot * 8 + lc * 2;
        *(float2*)&ob[(size_t)rbase * FOv + o] =
            make_float2(c[ot][0] * inv0, c[ot][1] * inv0);
        *(float2*)&ob[(size_t)(rbase + 8) * FOv + o] =
            make_float2(c[ot][2] * inv1, c[ot][3] * inv1);
    }
}

// ---------------- K4: head mean + bias + node mask (paired accumulators) ----------
__global__ void k_final(const float* __restrict__ mask, const float* __restrict__ bias,
                        float* __restrict__ out) {
    int idx = blockIdx.x * blockDim.x + threadIdx.x;
    int o4 = idx & 15;
    int n = (idx >> 4) & (Nn - 1);
    int b = idx >> 14;
    const float* base = &g_hout[(((size_t)(b * Hh)) * Nn + n) * FOv + o4 * 4];
    float4 acc0 = make_float4(0.f, 0.f, 0.f, 0.f);
    float4 acc1 = make_float4(0.f, 0.f, 0.f, 0.f);
    #pragma unroll
    for (int h = 0; h < 4; h++) {
        float4 v0 = *(const float4*)&base[(size_t)(2 * h) * Nn * FOv];
        float4 v1 = *(const float4*)&base[(size_t)(2 * h + 1) * Nn * FOv];
        acc0.x += v0.x; acc0.y += v0.y; acc0.z += v0.z; acc0.w += v0.w;
        acc1.x += v1.x; acc1.y += v1.y; acc1.z += v1.z; acc1.w += v1.w;
    }
    float4 acc = make_float4(acc0.x + acc1.x, acc0.y + acc1.y,
                             acc0.z + acc1.z, acc0.w + acc1.w);
    float mz = mask[b * Nn + n];
    float m8 = mz * 0.125f;
    float4 bv = *(const float4*)&bias[o4 * 4];
    float4 r;
    r.x = fmaf(acc.x, m8, mz * bv.x);
    r.y = fmaf(acc.y, m8, mz * bv.y);
    r.z = fmaf(acc.z, m8, mz * bv.z);
    r.w = fmaf(acc.w, m8, mz * bv.w);
    ((float4*)out)[idx] = r;
}

// ---------------- launch ----------------
extern "C" void kernel_launch(void* const* d_in, const int* in_sizes, int n_in,
                              void* d_out, int out_size) {
    const float* x     = (const float*)d_in[0];
    const int*   A     = (const int*)  d_in[1];
    const float* mask  = (const float*)d_in[2];
    const float* e     = (const float*)d_in[4];
    const float* Np    = (const float*)d_in[5];
    const float* w     = (const float*)d_in[6];
    const float* a_src = (const float*)d_in[7];
    const float* a_dst = (const float*)d_in[8];
    const float* bias  = (const float*)d_in[9];
    float* out = (float*)d_out;

    cudaFuncSetAttribute((const void*)k_feat,
                         cudaFuncAttributeMaxDynamicSharedMemorySize, FEAT_SMEM);

    k_pack <<<1024, 256>>>(A);
    k_feat <<<dim3(16, Bsz), 256, FEAT_SMEM>>>(x, e, Np, w, a_src, a_dst);
    k_attn <<<dim3(16, Hh, Bsz), 128>>>();
    k_final<<<512, 256>>>(mask, bias, out);
}

// round 15
// speedup vs baseline: 1.1251x; 1.1251x over previous
#include <cuda_runtime.h>
#include <cstdint>

#define Bsz 8
#define Nn 1024
#define Hh 8
#define FOv 64
#define FINv 256
#define LOG2E 1.4426950408889634f

// ---------------- device scratch ----------------
__device__ unsigned g_abits[Bsz * Nn * 32];                 // packed adjacency
__device__ float g_h[(size_t)Bsz * Hh * Nn * FOv];          // h[b][h][n][o] (tf32-rounded)
__device__ float g_s[Bsz * Hh * Nn];                        // pre-scaled by log2e
__device__ float g_d[Bsz * Hh * Nn];                        // pre-scaled by log2e
__device__ float g_hout[(size_t)Bsz * Hh * Nn * FOv];

// ---------------- helpers ----------------
static __device__ __forceinline__ uint32_t to_tf32(float f) {
    uint32_t u;
    asm("cvt.rna.tf32.f32 %0, %1;" : "=r"(u) : "f"(f));
    return u;
}
static __device__ __forceinline__ float ex2f(float x) {
    float y;
    asm("ex2.approx.f32 %0, %1;" : "=f"(y) : "f"(x));
    return y;
}
static __device__ __forceinline__ uint32_t smem_u32(const void* p) {
    uint32_t a;
    asm("{ .reg .u64 t; cvta.to.shared.u64 t, %1; cvt.u32.u64 %0, t; }" : "=r"(a) : "l"(p));
    return a;
}
static __device__ __forceinline__ void cpasync16(uint32_t s, const void* g) {
    asm volatile("cp.async.cg.shared.global [%0], [%1], 16;" :: "r"(s), "l"(g));
}
#define CP_COMMIT() asm volatile("cp.async.commit_group;" ::: "memory")
#define CP_WAIT(n)  asm volatile("cp.async.wait_group %0;" :: "n"(n) : "memory")
static __device__ __forceinline__ void mma_tf32(float* c, const uint32_t* a, uint32_t b0, uint32_t b1) {
    asm volatile(
        "mma.sync.aligned.m16n8k8.row.col.f32.tf32.tf32.f32 "
        "{%0,%1,%2,%3}, {%4,%5,%6,%7}, {%8,%9}, {%0,%1,%2,%3};"
        : "+f"(c[0]), "+f"(c[1]), "+f"(c[2]), "+f"(c[3])
        : "r"(a[0]), "r"(a[1]), "r"(a[2]), "r"(a[3]), "r"(b0), "r"(b1));
}

// ---------------- K1: MERGED prep kernel ----------------
// Blocks [0,128): feature GEMM (all heads) + fused s,d   (data: x,e,Np,w,a_src,a_dst)
// Blocks [128,1152): adjacency pack                       (data: A)
// Independent inputs -> the two phases overlap on-chip instead of serializing.
#define RECX_STRIDE 260
#define W_STRIDE 72
#define OFF_W    66560                       // recx: 64*260*4
#define OFF_ASD  (66560 + 147456)            // W: 2*256*72*4
#define FEAT_SMEM (OFF_ASD + 4096)           // asd: 1024 floats

__global__ __launch_bounds__(256) void k_prep(
    const int* __restrict__ A,
    const float* __restrict__ x, const float* __restrict__ e,
    const float* __restrict__ Np, const float* __restrict__ wg,
    const float* __restrict__ a_src, const float* __restrict__ a_dst)
{
    int tid = threadIdx.x;
    if (blockIdx.x >= 128) {
        // ---- pack branch: one warp per adjacency row, MLP 32 ----
        int p = blockIdx.x - 128;
        int warp = (p * 256 + tid) >> 5;
        int lane = tid & 31;
        const int* row = A + (size_t)warp * Nn;
        unsigned* dst = g_abits + warp * 32;
        int v[32];
        #pragma unroll
        for (int w = 0; w < 32; w++) v[w] = row[w * 32 + lane];
        #pragma unroll
        for (int w = 0; w < 32; w++) {
            unsigned bits = __ballot_sync(0xffffffffu, v[w] > 0);
            if (lane == 0) dst[w] = bits;
        }
        return;
    }
    // ---- feat branch ----
    extern __shared__ unsigned char sm_[];
    uint32_t* recx_s = (uint32_t*)sm_;
    uint32_t* W_s = (uint32_t*)(sm_ + OFF_W);
    float* asd_s = (float*)(sm_ + OFF_ASD);
    int fb = blockIdx.x;
    int nt = fb & 15, b = fb >> 4;
    int n0 = nt * 64;
    int wp = tid >> 5, lane = tid & 31;
    int gr = lane >> 2, lc = lane & 3;
    int hp = wp >> 2;
    int wr = (wp & 3) * 16;

    asd_s[tid] = a_src[tid];
    asd_s[tid + 256] = a_src[tid + 256];
    asd_s[512 + tid] = a_dst[tid];
    asd_s[768 + tid] = a_dst[tid + 256];

    {
        int rr = tid >> 2;
        int f0 = (tid & 3) * 64;
        const float* xrow = x + b * FINv;
        const float* np = Np + (size_t)(n0 + rr) * FINv;
        const float* ee = e + ((size_t)b * Nn + n0 + rr) * FINv;
        uint32_t* dstr = recx_s + rr * RECX_STRIDE + f0;
        #pragma unroll
        for (int i = 0; i < 16; i++) {
            float4 xv = *(const float4*)&xrow[f0 + i * 4];
            float4 nv = *(const float4*)&np[f0 + i * 4];
            float4 ev = *(const float4*)&ee[f0 + i * 4];
            dstr[i * 4 + 0] = to_tf32(xv.x * nv.x * ev.x);
            dstr[i * 4 + 1] = to_tf32(xv.y * nv.y * ev.y);
            dstr[i * 4 + 2] = to_tf32(xv.z * nv.z * ev.z);
            dstr[i * 4 + 3] = to_tf32(xv.w * nv.w * ev.w);
        }
    }

    for (int it = 0; it < 4; it++) {
        __syncthreads();
        {
            const float* wsrc = wg + (size_t)(it * 2) * FINv * FOv;
            #pragma unroll
            for (int i = 0; i < 32; i++) {
                int idx = i * 256 + tid;
                int hh = idx >> 12;
                int r = idx & 4095;
                int f = r >> 4, o4 = r & 15;
                float4 v = *(const float4*)&wsrc[(size_t)hh * FINv * FOv + f * FOv + o4 * 4];
                uint32_t* dd = W_s + hh * (256 * W_STRIDE) + f * W_STRIDE + o4 * 4;
                dd[0] = to_tf32(v.x); dd[1] = to_tf32(v.y);
                dd[2] = to_tf32(v.z); dd[3] = to_tf32(v.w);
            }
        }
        __syncthreads();
        int h = it * 2 + hp;
        const uint32_t* Wh = W_s + hp * (256 * W_STRIDE);
        float c[8][4];
        #pragma unroll
        for (int ot = 0; ot < 8; ot++)
            #pragma unroll
            for (int r = 0; r < 4; r++) c[ot][r] = 0.f;
        #pragma unroll
        for (int ks = 0; ks < 32; ks++) {
            uint32_t a[4];
            const uint32_t* ar0 = recx_s + (wr + gr) * RECX_STRIDE + ks * 8;
            const uint32_t* ar1 = ar0 + 8 * RECX_STRIDE;
            a[0] = ar0[lc]; a[1] = ar1[lc]; a[2] = ar0[lc + 4]; a[3] = ar1[lc + 4];
            const uint32_t* br0 = Wh + (ks * 8 + lc) * W_STRIDE + gr;
            const uint32_t* br1 = br0 + 4 * W_STRIDE;
            #pragma unroll
            for (int ot = 0; ot < 8; ot++)
                mma_tf32(c[ot], a, br0[ot * 8], br1[ot * 8]);
        }
        int bh = b * Hh + h;
        float* dsth = g_h + ((size_t)bh * Nn + n0 + wr) * FOv;
        const float* as = asd_s + h * 64;
        const float* ad = asd_s + 512 + h * 64;
        float s0 = 0.f, s1 = 0.f, d0 = 0.f, d1 = 0.f;
        #pragma unroll
        for (int ot = 0; ot < 8; ot++) {
            int o = ot * 8 + lc * 2;
            // store h tf32-ROUNDED: aggregation mma B-truncation becomes exact
            float2 hlo = make_float2(__uint_as_float(to_tf32(c[ot][0])),
                                     __uint_as_float(to_tf32(c[ot][1])));
            float2 hhi = make_float2(__uint_as_float(to_tf32(c[ot][2])),
                                     __uint_as_float(to_tf32(c[ot][3])));
            *(float2*)&dsth[(size_t)gr * FOv + o] = hlo;
            *(float2*)&dsth[(size_t)(gr + 8) * FOv + o] = hhi;
            float a0 = as[o], a1 = as[o + 1];
            float b0 = ad[o], b1 = ad[o + 1];
            s0 += c[ot][0] * a0 + c[ot][1] * a1;
            s1 += c[ot][2] * a0 + c[ot][3] * a1;
            d0 += c[ot][0] * b0 + c[ot][1] * b1;
            d1 += c[ot][2] * b0 + c[ot][3] * b1;
        }
        #pragma unroll
        for (int off = 1; off <= 2; off <<= 1) {
            s0 += __shfl_xor_sync(0xffffffffu, s0, off);
            s1 += __shfl_xor_sync(0xffffffffu, s1, off);
            d0 += __shfl_xor_sync(0xffffffffu, d0, off);
            d1 += __shfl_xor_sync(0xffffffffu, d1, off);
        }
        if (lc == 0) {
            int rb = bh * Nn + n0 + wr + gr;
            g_s[rb] = s0 * LOG2E; g_s[rb + 8] = s1 * LOG2E;
            g_d[rb] = d0 * LOG2E; g_d[rb + 8] = d1 * LOG2E;
        }
    }
}

// ---------------- K3: fused masked softmax + tf32 mma aggregation ----------------
// (R13-proven config: 128-row tiles, 4 warps x 32 rows, factorized exp, zero MUFU
// in hot loop, 3-stage cp.async, stride-72 conflict-free smem, 1 sync/chunk.)
#define HS_STR 72

__global__ void __launch_bounds__(128, 4) k_attn() {
    __shared__ uint32_t hs[3][32][HS_STR];   // h chunk (tf32-exact fp32 bits) [k=m][o]
    __shared__ float2 eds[Nn];               // (exp2(d), exp2(0.2 d)) per neighbor
    int tid = threadIdx.x;
    int w = tid >> 5, lane = tid & 31;
    int gr = lane >> 2, lc = lane & 3;
    int nt = blockIdx.x, h = blockIdx.y, b = blockIdx.z;
    int bh = b * Hh + h;
    int n0 = nt * 128;
    const float* hbase = g_h + (size_t)bh * Nn * FOv;

    {   // precompute neighbor exp table (one-time: 16 MUFU/thread)
        const float* dsrc = g_d + bh * Nn;
        #pragma unroll
        for (int i = 0; i < 8; i++) {
            int m = tid + i * 128;
            float dv = dsrc[m];
            eds[m] = make_float2(ex2f(dv), ex2f(0.2f * dv));
        }
    }
    int rbase = n0 + w * 32 + gr;
    float Es[4], Es2[4];
    const unsigned* bb[4];
    #pragma unroll
    for (int i = 0; i < 4; i++) {
        float sv = g_s[bh * Nn + rbase + i * 8];
        Es[i] = ex2f(sv);
        Es2[i] = ex2f(0.2f * sv);
        bb[i] = g_abits + (size_t)(b * Nn + rbase + i * 8) * 32;
    }

    float c[2][8][4];
    #pragma unroll
    for (int s2 = 0; s2 < 2; s2++)
        #pragma unroll
        for (int ot = 0; ot < 8; ot++)
            #pragma unroll
            for (int r = 0; r < 4; r++) c[s2][ot][r] = 0.f;
    float rs[4] = {0.f, 0.f, 0.f, 0.f};

    // staging coords: thread copies rows sm_+i*8 (i=0..3), 16B at col so4*4
    int sm_ = tid >> 4;
    int so4 = tid & 15;
    uint32_t hsb = smem_u32(hs);
    const float* gsrc = hbase + (size_t)sm_ * FOv + so4 * 4;

    // prologue: stage chunks 0,1 into bufs 0,1
    #pragma unroll
    for (int s = 0; s < 2; s++) {
        #pragma unroll
        for (int i = 0; i < 4; i++)
            cpasync16(hsb + (((unsigned)(s * 32 + sm_ + i * 8)) * HS_STR + so4 * 4) * 4,
                      gsrc + (s * 32 + i * 8) * FOv);
        CP_COMMIT();
    }

    for (int ch = 0; ch < 32; ch++) {
        int m0 = ch * 32;
        int buf = ch - (ch / 3) * 3;     // ch % 3
        if (ch < 31) CP_WAIT(1); else CP_WAIT(0);
        __syncthreads();

        unsigned bwv[4] = {bb[0][ch], bb[1][ch], bb[2][ch], bb[3][ch]};
        #pragma unroll
        for (int j = 0; j < 4; j++) {
            float2 eA = eds[m0 + j * 8 + lc];
            float2 eB = eds[m0 + j * 8 + lc + 4];
            int cc0 = j * 8 + lc, cc1 = cc0 + 4;
            uint32_t afr[2][4];
            #pragma unroll
            for (int sub = 0; sub < 2; sub++) {
                #pragma unroll
                for (int rr = 0; rr < 2; rr++) {
                    int ri = sub * 2 + rr;
                    float p1 = Es[ri] * eA.x;
                    float p2 = Es2[ri] * eA.y;
                    float w0 = (p1 > 1.f) ? p1 : p2;
                    w0 = ((bwv[ri] >> cc0) & 1u) ? w0 : 0.f;
                    float p3 = Es[ri] * eB.x;
                    float p4 = Es2[ri] * eB.y;
                    float w1 = (p3 > 1.f) ? p3 : p4;
                    w1 = ((bwv[ri] >> cc1) & 1u) ? w1 : 0.f;
                    uint32_t q0 = to_tf32(w0);
                    uint32_t q1 = to_tf32(w1);
                    afr[sub][rr]     = q0;
                    afr[sub][rr + 2] = q1;
                    rs[ri] += __uint_as_float(q0) + __uint_as_float(q1);
                }
            }
            #pragma unroll
            for (int ot = 0; ot < 8; ot++) {
                uint32_t b0 = hs[buf][j * 8 + lc][ot * 8 + gr];
                uint32_t b1 = hs[buf][j * 8 + lc + 4][ot * 8 + gr];
                mma_tf32(c[0][ot], afr[0], b0, b1);
                mma_tf32(c[1][ot], afr[1], b0, b1);
            }
        }
        if (ch < 30) {   // stage chunk ch+2 into buf (ch+2)%3
            int s = ch + 2;
            int nb = s - (s / 3) * 3;
            #pragma unroll
            for (int i = 0; i < 4; i++)
                cpasync16(hsb + (((unsigned)(nb * 32 + sm_ + i * 8)) * HS_STR + so4 * 4) * 4,
                          gsrc + (s * 32 + i * 8) * FOv);
            CP_COMMIT();
        }
    }
    #pragma unroll
    for (int i = 0; i < 4; i++) {
        rs[i] += __shfl_xor_sync(0xffffffffu, rs[i], 1);
        rs[i] += __shfl_xor_sync(0xffffffffu, rs[i], 2);
    }
    float inv[4];
    #pragma unroll
    for (int i = 0; i < 4; i++) inv[i] = 1.f / rs[i];

    float* ob = g_hout + (size_t)bh * Nn * FOv;
    #pragma unroll
    for (int sub = 0; sub < 2; sub++) {
        #pragma unroll
        for (int ot = 0; ot < 8; ot++) {
            int row = rbase + sub * 16;
            int o = ot * 8 + lc * 2;
            float2 lo = make_float2(c[sub][ot][0] * inv[sub * 2],
                                    c[sub][ot][1] * inv[sub * 2]);
            float2 hi = make_float2(c[sub][ot][2] * inv[sub * 2 + 1],
                                    c[sub][ot][3] * inv[sub * 2 + 1]);
            *(float2*)&ob[(size_t)row * FOv + o] = lo;
            *(float2*)&ob[(size_t)(row + 8) * FOv + o] = hi;
        }
    }
}

// ---------------- K4: head mean + bias + node mask (paired accumulators) ----------
__global__ void k_final(const float* __restrict__ mask, const float* __restrict__ bias,
                        float* __restrict__ out) {
    int idx = blockIdx.x * blockDim.x + threadIdx.x;
    int o4 = idx & 15;
    int n = (idx >> 4) & (Nn - 1);
    int b = idx >> 14;
    const float* base = &g_hout[(((size_t)(b * Hh)) * Nn + n) * FOv + o4 * 4];
    float4 acc0 = make_float4(0.f, 0.f, 0.f, 0.f);
    float4 acc1 = make_float4(0.f, 0.f, 0.f, 0.f);
    #pragma unroll
    for (int h = 0; h < 4; h++) {
        float4 v0 = *(const float4*)&base[(size_t)(2 * h) * Nn * FOv];
        float4 v1 = *(const float4*)&base[(size_t)(2 * h + 1) * Nn * FOv];
        acc0.x += v0.x; acc0.y += v0.y; acc0.z += v0.z; acc0.w += v0.w;
        acc1.x += v1.x; acc1.y += v1.y; acc1.z += v1.z; acc1.w += v1.w;
    }
    float4 acc = make_float4(acc0.x + acc1.x, acc0.y + acc1.y,
                             acc0.z + acc1.z, acc0.w + acc1.w);
    float mz = mask[b * Nn + n];
    float m8 = mz * 0.125f;
    float4 bv = *(const float4*)&bias[o4 * 4];
    float4 r;
    r.x = fmaf(acc.x, m8, mz * bv.x);
    r.y = fmaf(acc.y, m8, mz * bv.y);
    r.z = fmaf(acc.z, m8, mz * bv.z);
    r.w = fmaf(acc.w, m8, mz * bv.w);
    ((float4*)out)[idx] = r;
}

// ---------------- launch ----------------
extern "C" void kernel_launch(void* const* d_in, const int* in_sizes, int n_in,
                              void* d_out, int out_size) {
    const float* x     = (const float*)d_in[0];
    const int*   A     = (const int*)  d_in[1];
    const float* mask  = (const float*)d_in[2];
    const float* e     = (const float*)d_in[4];
    const float* Np    = (const float*)d_in[5];
    const float* w     = (const float*)d_in[6];
    const float* a_src = (const float*)d_in[7];
    const float* a_dst = (const float*)d_in[8];
    const float* bias  = (const float*)d_in[9];
    float* out = (float*)d_out;

    cudaFuncSetAttribute((const void*)k_prep,
                         cudaFuncAttributeMaxDynamicSharedMemorySize, FEAT_SMEM);

    k_prep <<<1152, 256, FEAT_SMEM>>>(A, x, e, Np, w, a_src, a_dst);
    k_attn <<<dim3(8, Hh, Bsz), 128>>>();
    k_final<<<512, 256>>>(mask, bias, out);
}